// round 1
// baseline (speedup 1.0000x reference)
#include <cuda_runtime.h>
#include <cuda_bf16.h>
#include <float.h>

#define FULL 0xFFFFFFFFu

static constexpr int B = 4;
static constexpr int N = 8192;
static constexpr int M = 2048;
static constexpr int F = 256;
static constexpr int K = 16;
static constexpr int OUTC = 3 + F;  // 259

// Scratch (device globals — no allocation allowed)
__device__ float g_featT[(size_t)B * N * F];   // 32MB transposed features (B,N,F)
__device__ int   g_idx[(size_t)B * M * K];
__device__ float g_w[(size_t)B * M * K];

// ---------------------------------------------------------------------------
// Kernel 1: KNN + weights + projected points.
// Warp per query. Block = 512 threads = 16 queries (same batch).
// Points staged through shared in 2048-point chunks as float4 (x,y,z,|p|^2).
// Ranking key: s = |p|^2 - 2 q.p  (|q|^2 dropped: monotonic, softmax-invariant).
// Warp-distributed sorted list: lane i holds i-th smallest (32 kept, 16 needed).
// ---------------------------------------------------------------------------
__global__ __launch_bounds__(512) void knn_kernel(
    const float* __restrict__ pc,     // (B,3,N)
    const float* __restrict__ qc,     // (B,3,M)
    const float* __restrict__ temperature,
    float* __restrict__ out)          // (B,259,M)
{
    __shared__ float4 s_pts[2048];

    const int tid  = threadIdx.x;
    const int lane = tid & 31;
    const int wid  = tid >> 5;
    const int b    = blockIdx.x >> 7;              // 128 blocks per batch
    const int m    = ((blockIdx.x & 127) << 4) + wid;

    const float* pcb = pc + (size_t)b * 3 * N;

    const float qx = qc[((size_t)b * 3 + 0) * M + m];
    const float qy = qc[((size_t)b * 3 + 1) * M + m];
    const float qz = qc[((size_t)b * 3 + 2) * M + m];
    const float ax = -2.0f * qx, ay = -2.0f * qy, az = -2.0f * qz;

    float kd = FLT_MAX;   // this lane's element of the warp-sorted list
    int   ki = 0;
    float thr = FLT_MAX;  // lazy copy of list element 15 (16th smallest)

    for (int c = 0; c < 4; ++c) {
        __syncthreads();
        // cooperative stage: 2048 points -> shared float4
        for (int i = tid; i < 2048; i += 512) {
            int n = c * 2048 + i;
            float x = pcb[n];
            float y = pcb[N + n];
            float z = pcb[2 * N + n];
            s_pts[i] = make_float4(x, y, z, fmaf(x, x, fmaf(y, y, z * z)));
        }
        __syncthreads();

        #pragma unroll 4
        for (int t = 0; t < 64; ++t) {
            float4 p = s_pts[t * 32 + lane];
            float s = fmaf(ax, p.x, p.w);
            s = fmaf(ay, p.y, s);
            s = fmaf(az, p.z, s);
            unsigned mask = __ballot_sync(FULL, s < thr);
            if (mask) {
                int nbase = c * 2048 + t * 32;
                do {
                    int src = __ffs(mask) - 1;
                    mask &= mask - 1;
                    float cd = __shfl_sync(FULL, s, src);
                    int   cn = nbase + src;
                    int pos = __popc(__ballot_sync(FULL, kd < cd));
                    float ud = __shfl_up_sync(FULL, kd, 1);
                    int   ui = __shfl_up_sync(FULL, ki, 1);
                    if (lane >= pos) {
                        kd = (lane == pos) ? cd : ud;
                        ki = (lane == pos) ? cn : ui;
                    }
                } while (mask);
                thr = __shfl_sync(FULL, kd, 15);
            }
        }
    }

    // softmax weights over the 16 smallest (shift-invariant: use s directly)
    float tv = *temperature;
    float sigma = fmaxf(tv * tv, 1e-4f);
    float inv_sigma = 1.0f / sigma;
    float s0 = __shfl_sync(FULL, kd, 0);
    float ev = (lane < K) ? __expf((s0 - kd) * inv_sigma) : 0.0f;
    float sum = ev;
    #pragma unroll
    for (int o = 16; o; o >>= 1) sum += __shfl_xor_sync(FULL, sum, o);
    float w = ev / sum;

    // projected points: sum_k w_k * p_k  (lanes >=16 contribute w=0)
    float px = pcb[ki];
    float py = pcb[N + ki];
    float pz = pcb[2 * N + ki];
    float sx = w * px, sy = w * py, sz = w * pz;
    #pragma unroll
    for (int o = 16; o; o >>= 1) {
        sx += __shfl_xor_sync(FULL, sx, o);
        sy += __shfl_xor_sync(FULL, sy, o);
        sz += __shfl_xor_sync(FULL, sz, o);
    }
    if (lane == 0) {
        out[((size_t)b * OUTC + 0) * M + m] = sx;
        out[((size_t)b * OUTC + 1) * M + m] = sy;
        out[((size_t)b * OUTC + 2) * M + m] = sz;
    }
    if (lane < K) {
        size_t gq = (size_t)b * M + m;
        g_idx[gq * K + lane] = ki;
        g_w[gq * K + lane]   = w;
    }
}

// ---------------------------------------------------------------------------
// Kernel 2: transpose features (B,F,N) -> (B,N,F)
// ---------------------------------------------------------------------------
__global__ void transpose_kernel(const float* __restrict__ feat)
{
    __shared__ float tile[32][33];
    int b  = blockIdx.z;
    int f0 = blockIdx.y * 32;
    int n0 = blockIdx.x * 32;
    int tx = threadIdx.x, ty = threadIdx.y;

    #pragma unroll
    for (int j = ty; j < 32; j += 8)
        tile[j][tx] = feat[((size_t)b * F + f0 + j) * N + n0 + tx];
    __syncthreads();
    #pragma unroll
    for (int j = ty; j < 32; j += 8)
        g_featT[((size_t)b * N + n0 + j) * F + f0 + tx] = tile[tx][j];
}

// ---------------------------------------------------------------------------
// Kernel 3: feature propagation. Block = 1024 threads = 32 queries.
// Warp per query: 16 neighbors x 2 LDG.128 per lane (contiguous 1KB vectors),
// accumulate 8 floats/lane, stage to shared, write out coalesced in (259,M).
// ---------------------------------------------------------------------------
__global__ __launch_bounds__(1024) void feat_kernel(float* __restrict__ out)
{
    __shared__ float so[32][260];  // [mLocal][f], stride 260 keeps 16B alignment

    const int tid  = threadIdx.x;
    const int lane = tid & 31;
    const int wid  = tid >> 5;
    const int b    = blockIdx.x >> 6;           // 64 blocks per batch
    const int m0   = (blockIdx.x & 63) * 32;
    const int m    = m0 + wid;
    const size_t gq = (size_t)b * M + m;

    int   iv = 0;
    float wv = 0.0f;
    if (lane < K) {
        iv = g_idx[gq * K + lane];
        wv = g_w[gq * K + lane];
    }

    float4 accA = make_float4(0.f, 0.f, 0.f, 0.f);
    float4 accB = make_float4(0.f, 0.f, 0.f, 0.f);

    #pragma unroll
    for (int j = 0; j < K; ++j) {
        float wj = __shfl_sync(FULL, wv, j);
        int   ij = __shfl_sync(FULL, iv, j);
        const float4* base = (const float4*)(g_featT + ((size_t)b * N + ij) * F);
        float4 u = base[lane];
        float4 v = base[32 + lane];
        accA.x = fmaf(wj, u.x, accA.x);
        accA.y = fmaf(wj, u.y, accA.y);
        accA.z = fmaf(wj, u.z, accA.z);
        accA.w = fmaf(wj, u.w, accA.w);
        accB.x = fmaf(wj, v.x, accB.x);
        accB.y = fmaf(wj, v.y, accB.y);
        accB.z = fmaf(wj, v.z, accB.z);
        accB.w = fmaf(wj, v.w, accB.w);
    }

    // lane covers f = 4*lane..4*lane+3 (accA) and 128+4*lane.. (accB)
    *(float4*)&so[wid][4 * lane]       = accA;
    *(float4*)&so[wid][128 + 4 * lane] = accB;
    __syncthreads();

    // write: warp wid handles f rows wid*8 .. wid*8+7; lanes = mLocal (coalesced)
    #pragma unroll
    for (int r = 0; r < 8; ++r) {
        int f = wid * 8 + r;
        out[((size_t)b * OUTC + 3 + f) * M + m0 + lane] = so[lane][f];
    }
}

// ---------------------------------------------------------------------------
extern "C" void kernel_launch(void* const* d_in, const int* in_sizes, int n_in,
                              void* d_out, int out_size)
{
    const float* pc   = (const float*)d_in[0];  // point_cloud (B,3,N)
    const float* qc   = (const float*)d_in[1];  // query_cloud (B,3,M)
    const float* feat = (const float*)d_in[2];  // point_features (B,F,N)
    const float* temp = (const float*)d_in[3];  // temperature scalar
    float* out = (float*)d_out;

    knn_kernel<<<(B * M) / 16, 512>>>(pc, qc, temp, out);
    transpose_kernel<<<dim3(N / 32, F / 32, B), dim3(32, 8)>>>(feat);
    feat_kernel<<<(B * M) / 32, 1024>>>(out);
}